// round 6
// baseline (speedup 1.0000x reference)
#include <cuda_runtime.h>
#include <cuda_fp16.h>
#include <math.h>
#include <stdint.h>

#define T_TOK   2048
#define DM      512
#define E_EXP   64
#define TOPK    8
#define H_GATE  1024
#define H_EXP   2048
#define NPAIR   (T_TOK*TOPK)

// ---------------- scratch (device globals) ----------------------------------
static __device__ float  g_h[(size_t)T_TOK * H_GATE];
static __device__ float  g_probs[T_TOK * E_EXP];
static __device__ float  g_topkw[T_TOK * TOPK];
static __device__ float  g_usage[E_EXP];
static __device__ int    g_count[E_EXP];
static __device__ int    g_list_t[E_EXP * T_TOK];
static __device__ int    g_list_p[E_EXP * T_TOK];
static __device__ __half g_x16[(size_t)T_TOK * DM];           // 2 MiB
static __device__ __half g_w1h[(size_t)E_EXP * DM * H_EXP];   // 128 MiB
static __device__ __half g_w2h[(size_t)E_EXP * H_EXP * DM];   // 128 MiB
static __device__ __half g_hidden16[(size_t)NPAIR * H_EXP];   // 64 MiB
static __device__ float  g_ybuf[(size_t)NPAIR * DM];          // 32 MiB

// ---------------- helpers ----------------------------------------------------
__device__ __forceinline__ uint32_t smem_u32(const void* p) {
    uint32_t a;
    asm("{ .reg .u64 t; cvta.to.shared.u64 t, %1; cvt.u32.u64 %0, t; }" : "=r"(a) : "l"(p));
    return a;
}
__device__ __forceinline__ uint32_t packh(float lo, float hi) {
    uint32_t r;
    asm("cvt.rn.f16x2.f32 %0, %1, %2;" : "=r"(r) : "f"(hi), "f"(lo));
    return r;
}
__device__ __forceinline__ void cp16(uint32_t dst, const void* src, int srcsize) {
    asm volatile("cp.async.cg.shared.global [%0], [%1], 16, %2;"
                 :: "r"(dst), "l"(src), "r"(srcsize) : "memory");
}
__device__ __forceinline__ void cp_commit() {
    asm volatile("cp.async.commit_group;" ::: "memory");
}
__device__ __forceinline__ void ldsm4(uint32_t* r, uint32_t addr) {
    asm volatile("ldmatrix.sync.aligned.m8n8.x4.shared.b16 {%0,%1,%2,%3}, [%4];"
                 : "=r"(r[0]), "=r"(r[1]), "=r"(r[2]), "=r"(r[3]) : "r"(addr));
}
__device__ __forceinline__ void ldsm4t(uint32_t* r, uint32_t addr) {
    asm volatile("ldmatrix.sync.aligned.m8n8.x4.trans.shared.b16 {%0,%1,%2,%3}, [%4];"
                 : "=r"(r[0]), "=r"(r[1]), "=r"(r[2]), "=r"(r[3]) : "r"(addr));
}
__device__ __forceinline__ void mma_f16(float* c, const uint32_t* a, uint32_t b0, uint32_t b1) {
    asm volatile(
        "mma.sync.aligned.m16n8k16.row.col.f32.f16.f16.f32 "
        "{%0,%1,%2,%3}, {%4,%5,%6,%7}, {%8,%9}, {%0,%1,%2,%3};"
        : "+f"(c[0]), "+f"(c[1]), "+f"(c[2]), "+f"(c[3])
        : "r"(a[0]), "r"(a[1]), "r"(a[2]), "r"(a[3]), "r"(b0), "r"(b1));
}

// ---------------- fp32 -> fp16 bulk convert ----------------------------------
__global__ void cvt16(const float4* __restrict__ in, uint4* __restrict__ out, int n8)
{
    int i = blockIdx.x * blockDim.x + threadIdx.x;
    if (i >= n8) return;
    float4 v0 = in[2 * i], v1 = in[2 * i + 1];
    uint4 o;
    o.x = packh(v0.x, v0.y); o.y = packh(v0.z, v0.w);
    o.z = packh(v1.x, v1.y); o.w = packh(v1.z, v1.w);
    out[i] = o;
}

// ---------------- all-fp16 grouped GEMM: cp.async + ldmatrix + HMMA ----------
// C[out(r), n] = act( sum_k A[in(r), k] * B[e][k, n] + bias[e][n] )
// A fp16 [*, lda] row-major; B fp16 [K][N]. Tile 128x128, BK=64, 8 warps (32x64).
// SMEM stage: A 128x64 fp16 (128B rows, 16B XOR swizzle), B 64x128 fp16 (256B rows).
template<typename OT, int ACT>
__global__ __launch_bounds__(256, 2)
void mma_gemm16(const __half* __restrict__ A, int lda, int K,
                const __half* __restrict__ Bbase, size_t strideB, int N,
                const float* __restrict__ biasBase, int strideBias,
                OT* __restrict__ C, int ldc,
                const int* __restrict__ rowlist, const int* __restrict__ outlist,
                const int* __restrict__ cnts, int Mfixed)
{
    const int e  = blockIdx.z;
    const int M  = cnts ? cnts[e] : Mfixed;
    const int m0 = blockIdx.x * 128;
    if (m0 >= M) return;
    const int n0 = blockIdx.y * 128;

    extern __shared__ char sm[];
    const uint32_t smBytes = smem_u32(sm);

    const int tid  = threadIdx.x;
    const int wid  = tid >> 5;
    const int lane = tid & 31;
    const int wy   = wid & 3;
    const int wx   = wid >> 2;
    const int g    = lane >> 2;
    const int tig  = lane & 3;

    const __half* B = Bbase + (size_t)e * strideB;
    const int* rl = rowlist ? rowlist + e * T_TOK : nullptr;
    const int* ol = outlist ? outlist + e * T_TOK : nullptr;

    // ---- cp.async staging assignments (4 A-chunks + 4 B-chunks of 16B) -----
    const __half* aSrc[4]; uint32_t aOff[4]; int aSz[4];
    const __half* bSrc[4]; uint32_t bOff[4];
    #pragma unroll
    for (int j = 0; j < 4; j++) {
        int idx = tid + j * 256;
        int ar = idx >> 3, s = idx & 7;                    // A: row, 16B seg
        aOff[j] = (uint32_t)(ar * 128 + 16 * (s ^ (ar & 7)));
        int gm = m0 + ar;
        if (gm < M) { aSrc[j] = A + (size_t)(rl ? rl[gm] : gm) * lda + s * 8; aSz[j] = 16; }
        else        { aSrc[j] = A;                                            aSz[j] = 0;  }
        int bk = idx >> 4, s2 = idx & 15;                  // B: k-row, 16B seg
        bOff[j] = 16384u + (uint32_t)(bk * 256 + 16 * (s2 ^ (bk & 7)));
        bSrc[j] = B + (size_t)bk * N + n0 + s2 * 8;
    }

    const int NC = K / 64;
    const size_t bStep = (size_t)64 * N;

    #define ISSUE(cc) do { \
        uint32_t st = smBytes + (uint32_t)((cc) % 3) * 32768u; \
        _Pragma("unroll") \
        for (int j = 0; j < 4; j++) cp16(st + aOff[j], aSrc[j] + (size_t)(cc) * 64, aSz[j]); \
        _Pragma("unroll") \
        for (int j = 0; j < 4; j++) cp16(st + bOff[j], bSrc[j] + (size_t)(cc) * bStep, 16); \
        cp_commit(); \
    } while (0)

    ISSUE(0);
    if (NC > 1) ISSUE(1);

    float acc[2][8][4];
    #pragma unroll
    for (int fm = 0; fm < 2; fm++)
        #pragma unroll
        for (int fn = 0; fn < 8; fn++)
            #pragma unroll
            for (int q = 0; q < 4; q++) acc[fm][fn][q] = 0.f;

    // ldmatrix lane constants
    const int mlane = wy * 32 + (lane & 15);     // A row for this lane (fm0)
    const int aksel = (lane >> 4) & 1;           // A k-seg select (+8 halfs)
    const int bklan = lane & 15;                 // B k-row offset
    const int bnsel = ((lane >> 4) & 1) * 8;     // B n offset (+8)

    for (int c = 0; c < NC; c++) {
        if (c + 1 < NC) asm volatile("cp.async.wait_group 1;" ::: "memory");
        else            asm volatile("cp.async.wait_group 0;" ::: "memory");
        __syncthreads();

        if (c + 2 < NC) ISSUE(c + 2);

        const uint32_t stA = smBytes + (uint32_t)(c % 3) * 32768u;
        const uint32_t stB = stA + 16384u;

        #pragma unroll
        for (int ks = 0; ks < 4; ks++) {
            const int aseg = ks * 2 + aksel;     // 16B segment index 0..7
            uint32_t a0[4], a1[4];
            {
                int m = mlane;
                ldsm4(a0, stA + m * 128 + 16 * (aseg ^ (m & 7)));
                m = mlane + 16;
                ldsm4(a1, stA + m * 128 + 16 * (aseg ^ (m & 7)));
            }
            const int kk = ks * 16 + bklan;
            const uint32_t brow = stB + kk * 256;
            const int ksw = kk & 7;
            #pragma unroll
            for (int nb = 0; nb < 4; nb++) {
                int nseg = (wx * 64 + nb * 16 + bnsel) >> 3;
                uint32_t bb[4];
                ldsm4t(bb, brow + 16 * (nseg ^ ksw));
                mma_f16(acc[0][2 * nb],     a0, bb[0], bb[1]);
                mma_f16(acc[1][2 * nb],     a1, bb[0], bb[1]);
                mma_f16(acc[0][2 * nb + 1], a0, bb[2], bb[3]);
                mma_f16(acc[1][2 * nb + 1], a1, bb[2], bb[3]);
            }
        }
        __syncthreads();
    }
    #undef ISSUE

    // ---- epilogue -----------------------------------------------------------
    const float* bias = biasBase + (size_t)e * strideBias + n0;
    #pragma unroll
    for (int fm = 0; fm < 2; fm++) {
        int r0 = m0 + wy * 32 + fm * 16 + g;
        #pragma unroll
        for (int half = 0; half < 2; half++) {
            int row = r0 + half * 8;
            if (row >= M) continue;
            int orow = ol ? ol[row] : row;
            OT* cp = C + (size_t)orow * ldc + n0;
            #pragma unroll
            for (int fn = 0; fn < 8; fn++) {
                int col = wx * 64 + fn * 8 + 2 * tig;
                float v0 = acc[fm][fn][half * 2 + 0] + bias[col];
                float v1 = acc[fm][fn][half * 2 + 1] + bias[col + 1];
                if (ACT == 2) {
                    v0 = 0.5f * v0 * (1.f + erff(v0 * 0.70710678118654752f));
                    v1 = 0.5f * v1 * (1.f + erff(v1 * 0.70710678118654752f));
                }
                if (sizeof(OT) == 4) {
                    *(float2*)((float*)cp + col) = make_float2(v0, v1);
                } else {
                    *(uint32_t*)((__half*)cp + col) = packh(v0, v1);
                }
            }
        }
    }
}

// ---------------- fp32 SGEMM (gate layer 1 — precision-critical) ------------
__global__ __launch_bounds__(256)
void sgemm_relu(const float* __restrict__ A, int lda, int K,
                const float* __restrict__ B, int N,
                const float* __restrict__ bias,
                float* __restrict__ C, int ldc)
{
    const int m0 = blockIdx.x * 128;
    const int n0 = blockIdx.y * 128;

    __shared__ float As[8][128];
    __shared__ float Bs[8][128];

    const int tid  = threadIdx.x;
    const int arow = tid >> 1;
    const int acol = (tid & 1) * 4;
    const float* aptr = A + (size_t)(m0 + arow) * lda + acol;
    const float* bptr = B + (size_t)(tid >> 5) * N + n0 + (tid & 31) * 4;
    const int ty = tid >> 4, tx = tid & 15;

    float acc[8][8];
    #pragma unroll
    for (int i = 0; i < 8; i++)
        #pragma unroll
        for (int j = 0; j < 8; j++) acc[i][j] = 0.f;

    for (int k0 = 0; k0 < K; k0 += 8) {
        float4 av = *(const float4*)(aptr + k0);
        float4 bv = *(const float4*)(bptr + (size_t)k0 * N);
        As[acol + 0][arow] = av.x; As[acol + 1][arow] = av.y;
        As[acol + 2][arow] = av.z; As[acol + 3][arow] = av.w;
        *(float4*)&Bs[tid >> 5][(tid & 31) * 4] = bv;
        __syncthreads();
        #pragma unroll
        for (int kk = 0; kk < 8; kk++) {
            float rA[8], rB[8];
            *(float4*)&rA[0] = *(const float4*)&As[kk][ty * 8];
            *(float4*)&rA[4] = *(const float4*)&As[kk][ty * 8 + 4];
            *(float4*)&rB[0] = *(const float4*)&Bs[kk][tx * 8];
            *(float4*)&rB[4] = *(const float4*)&Bs[kk][tx * 8 + 4];
            #pragma unroll
            for (int i = 0; i < 8; i++)
                #pragma unroll
                for (int j = 0; j < 8; j++)
                    acc[i][j] = fmaf(rA[i], rB[j], acc[i][j]);
        }
        __syncthreads();
    }
    #pragma unroll
    for (int i = 0; i < 8; i++) {
        float* cp = C + (size_t)(m0 + ty * 8 + i) * ldc + n0 + tx * 8;
        float v[8];
        #pragma unroll
        for (int j = 0; j < 8; j++)
            v[j] = fmaxf(acc[i][j] + bias[n0 + tx * 8 + j], 0.f);
        *(float4*)(cp)     = make_float4(v[0], v[1], v[2], v[3]);
        *(float4*)(cp + 4) = make_float4(v[4], v[5], v[6], v[7]);
    }
}

// ---------------- gating: logits + softmax + top-8 + routing ----------------
__global__ void gate_route_kernel(const float* __restrict__ h,
                                  const float* __restrict__ w2,
                                  const float* __restrict__ b2)
{
    __shared__ float hs[H_GATE];
    __shared__ float red[E_EXP];
    __shared__ int   ridx[E_EXP];
    __shared__ float pv[E_EXP];
    __shared__ float selw[TOPK];
    __shared__ int   seli[TOPK];

    const int t = blockIdx.x;
    const int tid = threadIdx.x;

    for (int i = tid; i < H_GATE; i += E_EXP) hs[i] = h[(size_t)t * H_GATE + i];
    __syncthreads();

    float acc = b2[tid];
    #pragma unroll 8
    for (int kk = 0; kk < H_GATE; kk++)
        acc = fmaf(hs[kk], w2[kk * E_EXP + tid], acc);

    red[tid] = acc; __syncthreads();
    for (int s = 32; s > 0; s >>= 1) { if (tid < s) red[tid] = fmaxf(red[tid], red[tid + s]); __syncthreads(); }
    float m = red[0]; __syncthreads();
    float p = expf(acc - m);
    red[tid] = p; __syncthreads();
    for (int s = 32; s > 0; s >>= 1) { if (tid < s) red[tid] += red[tid + s]; __syncthreads(); }
    float sum = red[0]; __syncthreads();
    p /= sum;
    g_probs[t * E_EXP + tid] = p;

    pv[tid] = p; __syncthreads();
    for (int k = 0; k < TOPK; k++) {
        red[tid] = pv[tid]; ridx[tid] = tid; __syncthreads();
        for (int s = 32; s > 0; s >>= 1) {
            if (tid < s) {
                if (red[tid + s] > red[tid] ||
                    (red[tid + s] == red[tid] && ridx[tid + s] < ridx[tid])) {
                    red[tid] = red[tid + s]; ridx[tid] = ridx[tid + s];
                }
            }
            __syncthreads();
        }
        if (tid == 0) { seli[k] = ridx[0]; selw[k] = red[0]; pv[ridx[0]] = -1.f; }
        __syncthreads();
    }

    if (tid == 0) {
        float s8 = 0.f;
        #pragma unroll
        for (int k = 0; k < TOPK; k++) s8 += selw[k];
        float inv = 1.f / s8;
        for (int k = 0; k < TOPK; k++) {
            int ee = seli[k];
            g_topkw[t * TOPK + k] = selw[k] * inv;
            int pos = atomicAdd(&g_count[ee], 1);
            g_list_t[ee * T_TOK + pos] = t;
            g_list_p[ee * T_TOK + pos] = t * TOPK + k;
        }
    }
}

// ---------------- load-balance loss -------------------------------------------
__global__ void usage_kernel()
{
    __shared__ float red[128];
    const int e = blockIdx.x;
    float s = 0.f;
    for (int t = threadIdx.x; t < T_TOK; t += 128) s += g_probs[t * E_EXP + e];
    red[threadIdx.x] = s; __syncthreads();
    for (int st = 64; st > 0; st >>= 1) { if (threadIdx.x < st) red[threadIdx.x] += red[threadIdx.x + st]; __syncthreads(); }
    if (threadIdx.x == 0) {
        float u = red[0] / (float)T_TOK - 1.f / (float)E_EXP;
        g_usage[e] = u * u;
    }
}
__global__ void lb_final(float* __restrict__ out, int out_size)
{
    __shared__ float red[E_EXP];
    const int e = threadIdx.x;
    red[e] = g_usage[e]; __syncthreads();
    for (int st = 32; st > 0; st >>= 1) { if (e < st) red[e] += red[e + st]; __syncthreads(); }
    if (e == 0 && out_size > T_TOK * DM)
        out[T_TOK * DM] = 0.01f * red[0] / (float)E_EXP;
}

// ---------------- weighted combine -------------------------------------------
__global__ void combine_kernel(float* __restrict__ out)
{
    const int t = blockIdx.x;
    for (int d = threadIdx.x; d < DM; d += 256) {
        float a = 0.f;
        #pragma unroll
        for (int k = 0; k < TOPK; k++)
            a = fmaf(g_topkw[t * TOPK + k],
                     g_ybuf[(size_t)(t * TOPK + k) * DM + d], a);
        out[(size_t)t * DM + d] = a;
    }
}

__global__ void zero_counts() { g_count[threadIdx.x] = 0; }

// ---------------- launch ------------------------------------------------------
extern "C" void kernel_launch(void* const* d_in, const int* in_sizes, int n_in,
                              void* d_out, int out_size)
{
    const float* x   = (const float*)d_in[0];
    const float* gw1 = (const float*)d_in[1];
    const float* gb1 = (const float*)d_in[2];
    const float* gw2 = (const float*)d_in[3];
    const float* gb2 = (const float*)d_in[4];
    const float* ew1 = (const float*)d_in[5];
    const float* eb1 = (const float*)d_in[6];
    const float* ew2 = (const float*)d_in[7];
    const float* eb2 = (const float*)d_in[8];
    float* out = (float*)d_out;

    float *ph, *pybuf;
    __half *phid, *px16, *pw1h, *pw2h;
    int *pcnt, *plt, *plp;
    cudaGetSymbolAddress((void**)&ph,    g_h);
    cudaGetSymbolAddress((void**)&phid,  g_hidden16);
    cudaGetSymbolAddress((void**)&px16,  g_x16);
    cudaGetSymbolAddress((void**)&pw1h,  g_w1h);
    cudaGetSymbolAddress((void**)&pw2h,  g_w2h);
    cudaGetSymbolAddress((void**)&pybuf, g_ybuf);
    cudaGetSymbolAddress((void**)&pcnt,  g_count);
    cudaGetSymbolAddress((void**)&plt,   g_list_t);
    cudaGetSymbolAddress((void**)&plp,   g_list_p);

    const int SMEM_DYN = 3 * 32768;   // 96 KB
    cudaFuncSetAttribute((const void*)mma_gemm16<__half, 2>,
                         cudaFuncAttributeMaxDynamicSharedMemorySize, SMEM_DYN);
    cudaFuncSetAttribute((const void*)mma_gemm16<float, 0>,
                         cudaFuncAttributeMaxDynamicSharedMemorySize, SMEM_DYN);

    zero_counts<<<1, E_EXP>>>();

    // fp16 conversions (weights + activations)
    {
        int n8w = (E_EXP * DM * H_EXP) / 8;
        cvt16<<<(n8w + 255) / 256, 256>>>((const float4*)ew1, (uint4*)pw1h, n8w);
        cvt16<<<(n8w + 255) / 256, 256>>>((const float4*)ew2, (uint4*)pw2h, n8w);
        int n8x = (T_TOK * DM) / 8;
        cvt16<<<(n8x + 255) / 256, 256>>>((const float4*)x, (uint4*)px16, n8x);
    }

    // gate layer 1 (exact fp32 — routing depends on it)
    sgemm_relu<<<dim3(T_TOK/128, H_GATE/128), 256>>>(x, DM, DM, gw1, H_GATE, gb1, ph, H_GATE);

    gate_route_kernel<<<T_TOK, E_EXP>>>(ph, gw2, gb2);

    usage_kernel<<<E_EXP, 128>>>();
    lb_final<<<1, E_EXP>>>(out, out_size);

    // expert GEMM 1: hidden16 = gelu(x16[list] @ w1h[e] + eb1[e])
    mma_gemm16<__half, 2><<<dim3(T_TOK/128, H_EXP/128, E_EXP), 256, SMEM_DYN>>>(
        px16, DM, DM, pw1h, (size_t)DM * H_EXP, H_EXP, eb1, H_EXP,
        phid, H_EXP, plt, plp, pcnt, 0);

    // expert GEMM 2: ybuf = hidden16[list] @ w2h[e] + eb2[e]
    mma_gemm16<float, 0><<<dim3(T_TOK/128, DM/128, E_EXP), 256, SMEM_DYN>>>(
        phid, H_EXP, H_EXP, pw2h, (size_t)H_EXP * DM, DM, eb2, DM,
        pybuf, DM, plp, plp, pcnt, 0);

    combine_kernel<<<T_TOK, 256>>>(out);
}

// round 8
// speedup vs baseline: 1.4122x; 1.4122x over previous
#include <cuda_runtime.h>
#include <cuda_fp16.h>
#include <math.h>
#include <stdint.h>

#define T_TOK   2048
#define DM      512
#define E_EXP   64
#define TOPK    8
#define H_GATE  1024
#define H_EXP   2048
#define NPAIR   (T_TOK*TOPK)
#define UPART   32

// ---------------- scratch (device globals) ----------------------------------
static __device__ float  g_h[(size_t)T_TOK * H_GATE];        // gate hidden fp32
static __device__ float  g_probs[T_TOK * E_EXP];
static __device__ float  g_topkw[T_TOK * TOPK];
static __device__ float  g_part[UPART][E_EXP];
static __device__ int    g_count[E_EXP];
static __device__ int    g_list_t[E_EXP * T_TOK];
static __device__ int    g_list_p[E_EXP * T_TOK];
static __device__ __half g_x16[(size_t)T_TOK * DM];          // 2 MiB
static __device__ __half g_w1h[(size_t)E_EXP * DM * H_EXP];  // 128 MiB
static __device__ __half g_w2h[(size_t)E_EXP * H_EXP * DM];  // 128 MiB
static __device__ __half g_hidden16[(size_t)NPAIR * H_EXP];  // 64 MiB
static __device__ float  g_ybuf[(size_t)NPAIR * DM];         // 32 MiB

// ---------------- helpers ----------------------------------------------------
__device__ __forceinline__ uint32_t smem_u32(const void* p) {
    uint32_t a;
    asm("{ .reg .u64 t; cvta.to.shared.u64 t, %1; cvt.u32.u64 %0, t; }" : "=r"(a) : "l"(p));
    return a;
}
__device__ __forceinline__ uint32_t packh(float lo, float hi) {
    uint32_t r;
    asm("cvt.rn.f16x2.f32 %0, %1, %2;" : "=r"(r) : "f"(hi), "f"(lo));
    return r;
}
__device__ __forceinline__ void cp16(uint32_t dst, const void* src, int srcsize) {
    asm volatile("cp.async.cg.shared.global [%0], [%1], 16, %2;"
                 :: "r"(dst), "l"(src), "r"(srcsize) : "memory");
}
__device__ __forceinline__ void cp_commit() {
    asm volatile("cp.async.commit_group;" ::: "memory");
}
__device__ __forceinline__ void ldsm4(uint32_t* r, uint32_t addr) {
    asm volatile("ldmatrix.sync.aligned.m8n8.x4.shared.b16 {%0,%1,%2,%3}, [%4];"
                 : "=r"(r[0]), "=r"(r[1]), "=r"(r[2]), "=r"(r[3]) : "r"(addr));
}
__device__ __forceinline__ void ldsm4t(uint32_t* r, uint32_t addr) {
    asm volatile("ldmatrix.sync.aligned.m8n8.x4.trans.shared.b16 {%0,%1,%2,%3}, [%4];"
                 : "=r"(r[0]), "=r"(r[1]), "=r"(r[2]), "=r"(r[3]) : "r"(addr));
}
__device__ __forceinline__ void mma_f16(float* c, const uint32_t* a, uint32_t b0, uint32_t b1) {
    asm volatile(
        "mma.sync.aligned.m16n8k16.row.col.f32.f16.f16.f32 "
        "{%0,%1,%2,%3}, {%4,%5,%6,%7}, {%8,%9}, {%0,%1,%2,%3};"
        : "+f"(c[0]), "+f"(c[1]), "+f"(c[2]), "+f"(c[3])
        : "r"(a[0]), "r"(a[1]), "r"(a[2]), "r"(a[3]), "r"(b0), "r"(b1));
}

// ---------------- fp32 -> fp16 bulk convert (grid-stride, saturating) --------
__global__ void cvt16(const float4* __restrict__ in, uint4* __restrict__ out, int n8)
{
    int stride = gridDim.x * blockDim.x;
    for (int i = blockIdx.x * blockDim.x + threadIdx.x; i < n8; i += stride) {
        float4 v0 = __ldg(&in[2 * i]);
        float4 v1 = __ldg(&in[2 * i + 1]);
        uint4 o;
        o.x = packh(v0.x, v0.y); o.y = packh(v0.z, v0.w);
        o.z = packh(v1.x, v1.y); o.w = packh(v1.z, v1.w);
        out[i] = o;
    }
}

// ---------------- all-fp16 grouped GEMM: cp.async + ldmatrix + HMMA ----------
// C[out(r), n] = act( sum_k A[in(r), k] * B[e][k, n] + bias[e][n] )
// Tile 128x128, BK=64, 8 warps (32x64). ACT: 0 none, 2 gelu.
template<typename OT, int ACT>
__global__ __launch_bounds__(256, 2)
void mma_gemm16(const __half* __restrict__ A, int lda, int K,
                const __half* __restrict__ Bbase, size_t strideB, int N,
                const float* __restrict__ biasBase, int strideBias,
                OT* __restrict__ C, int ldc,
                const int* __restrict__ rowlist, const int* __restrict__ outlist,
                const int* __restrict__ cnts, int Mfixed)
{
    const int e  = blockIdx.z;
    const int M  = cnts ? cnts[e] : Mfixed;
    const int m0 = blockIdx.x * 128;
    if (m0 >= M) return;
    const int n0 = blockIdx.y * 128;

    extern __shared__ char sm[];
    const uint32_t smBytes = smem_u32(sm);

    const int tid  = threadIdx.x;
    const int wid  = tid >> 5;
    const int lane = tid & 31;
    const int wy   = wid & 3;
    const int wx   = wid >> 2;
    const int g    = lane >> 2;
    const int tig  = lane & 3;

    const int* rl = rowlist ? rowlist + e * T_TOK : nullptr;
    const int* ol = outlist ? outlist + e * T_TOK : nullptr;

    // ---- cp.async staging: A needs 4 gathered pointers; the rest derived ----
    const __half* aSrc[4]; int aSz[4];
    uint32_t aOff0, bOff0;
    const __half* bSrc0;
    {
        int ar = tid >> 3, s = tid & 7;
        aOff0 = (uint32_t)(ar * 128 + 16 * (s ^ (ar & 7)));
        #pragma unroll
        for (int j = 0; j < 4; j++) {
            int gm = m0 + ar + j * 32;
            if (gm < M) { aSrc[j] = A + (size_t)(rl ? rl[gm] : gm) * lda + s * 8; aSz[j] = 16; }
            else        { aSrc[j] = A;                                            aSz[j] = 0;  }
        }
        int bk = tid >> 4, s2 = tid & 15;
        bOff0 = 16384u + (uint32_t)(bk * 256 + 16 * (s2 ^ (bk & 7)));
        bSrc0 = Bbase + (size_t)e * strideB + (size_t)bk * N + n0 + s2 * 8;
    }

    const int NC = K / 64;
    const size_t bStep = (size_t)64 * N;

    #define ISSUE(cc) do { \
        uint32_t st = smBytes + (uint32_t)((cc) % 3) * 32768u; \
        _Pragma("unroll") \
        for (int j = 0; j < 4; j++) \
            cp16(st + aOff0 + (uint32_t)j * 4096u, aSrc[j] + (size_t)(cc) * 64, aSz[j]); \
        _Pragma("unroll") \
        for (int j = 0; j < 4; j++) \
            cp16(st + bOff0 + (uint32_t)j * 4096u, bSrc0 + (size_t)j * 16 * N + (size_t)(cc) * bStep, 16); \
        cp_commit(); \
    } while (0)

    ISSUE(0);
    if (NC > 1) ISSUE(1);

    float acc[2][8][4];
    #pragma unroll
    for (int fm = 0; fm < 2; fm++)
        #pragma unroll
        for (int fn = 0; fn < 8; fn++)
            #pragma unroll
            for (int q = 0; q < 4; q++) acc[fm][fn][q] = 0.f;

    const int mlane = wy * 32 + (lane & 15);
    const int aksel = (lane >> 4) & 1;
    const int bklan = lane & 15;
    const int bnsel = ((lane >> 4) & 1) * 8;

    for (int c = 0; c < NC; c++) {
        if (c + 1 < NC) asm volatile("cp.async.wait_group 1;" ::: "memory");
        else            asm volatile("cp.async.wait_group 0;" ::: "memory");
        __syncthreads();

        if (c + 2 < NC) ISSUE(c + 2);

        const uint32_t stA = smBytes + (uint32_t)(c % 3) * 32768u;
        const uint32_t stB = stA + 16384u;

        #pragma unroll
        for (int ks = 0; ks < 4; ks++) {
            const int aseg = ks * 2 + aksel;
            uint32_t a0[4], a1[4];
            {
                int m = mlane;
                ldsm4(a0, stA + m * 128 + 16 * (aseg ^ (m & 7)));
                m = mlane + 16;
                ldsm4(a1, stA + m * 128 + 16 * (aseg ^ (m & 7)));
            }
            const int kk = ks * 16 + bklan;
            const uint32_t brow = stB + kk * 256;
            const int ksw = kk & 7;
            #pragma unroll
            for (int nb = 0; nb < 4; nb++) {
                int nseg = (wx * 64 + nb * 16 + bnsel) >> 3;
                uint32_t bb[4];
                ldsm4t(bb, brow + 16 * (nseg ^ ksw));
                mma_f16(acc[0][2 * nb],     a0, bb[0], bb[1]);
                mma_f16(acc[1][2 * nb],     a1, bb[0], bb[1]);
                mma_f16(acc[0][2 * nb + 1], a0, bb[2], bb[3]);
                mma_f16(acc[1][2 * nb + 1], a1, bb[2], bb[3]);
            }
        }
        __syncthreads();
    }
    #undef ISSUE

    // ---- epilogue -----------------------------------------------------------
    const float* bias = biasBase + (size_t)e * strideBias + n0;
    #pragma unroll
    for (int fm = 0; fm < 2; fm++) {
        int r0 = m0 + wy * 32 + fm * 16 + g;
        #pragma unroll
        for (int half = 0; half < 2; half++) {
            int row = r0 + half * 8;
            if (row >= M) continue;
            int orow = ol ? ol[row] : row;
            OT* cp = C + (size_t)orow * ldc + n0;
            #pragma unroll
            for (int fn = 0; fn < 8; fn++) {
                int col = wx * 64 + fn * 8 + 2 * tig;
                float v0 = acc[fm][fn][half * 2 + 0] + bias[col];
                float v1 = acc[fm][fn][half * 2 + 1] + bias[col + 1];
                if (ACT == 2) {
                    v0 = 0.5f * v0 * (1.f + erff(v0 * 0.70710678118654752f));
                    v1 = 0.5f * v1 * (1.f + erff(v1 * 0.70710678118654752f));
                }
                if (sizeof(OT) == 4) {
                    *(float2*)((float*)cp + col) = make_float2(v0, v1);
                } else {
                    *(uint32_t*)((__half*)cp + col) = packh(v0, v1);
                }
            }
        }
    }
}

// ---------------- fp32 SGEMM (gate layer 1 — precision-critical, PINNED) -----
__global__ __launch_bounds__(256)
void sgemm_relu(const float* __restrict__ A, int lda, int K,
                const float* __restrict__ B, int N,
                const float* __restrict__ bias,
                float* __restrict__ C, int ldc)
{
    const int m0 = blockIdx.x * 128;
    const int n0 = blockIdx.y * 128;

    __shared__ float As[8][128];
    __shared__ float Bs[8][128];

    const int tid  = threadIdx.x;
    const int arow = tid >> 1;
    const int acol = (tid & 1) * 4;
    const float* aptr = A + (size_t)(m0 + arow) * lda + acol;
    const float* bptr = B + (size_t)(tid >> 5) * N + n0 + (tid & 31) * 4;
    const int ty = tid >> 4, tx = tid & 15;

    float acc[8][8];
    #pragma unroll
    for (int i = 0; i < 8; i++)
        #pragma unroll
        for (int j = 0; j < 8; j++) acc[i][j] = 0.f;

    for (int k0 = 0; k0 < K; k0 += 8) {
        float4 av = *(const float4*)(aptr + k0);
        float4 bv = *(const float4*)(bptr + (size_t)k0 * N);
        As[acol + 0][arow] = av.x; As[acol + 1][arow] = av.y;
        As[acol + 2][arow] = av.z; As[acol + 3][arow] = av.w;
        *(float4*)&Bs[tid >> 5][(tid & 31) * 4] = bv;
        __syncthreads();
        #pragma unroll
        for (int kk = 0; kk < 8; kk++) {
            float rA[8], rB[8];
            *(float4*)&rA[0] = *(const float4*)&As[kk][ty * 8];
            *(float4*)&rA[4] = *(const float4*)&As[kk][ty * 8 + 4];
            *(float4*)&rB[0] = *(const float4*)&Bs[kk][tx * 8];
            *(float4*)&rB[4] = *(const float4*)&Bs[kk][tx * 8 + 4];
            #pragma unroll
            for (int i = 0; i < 8; i++)
                #pragma unroll
                for (int j = 0; j < 8; j++)
                    acc[i][j] = fmaf(rA[i], rB[j], acc[i][j]);
        }
        __syncthreads();
    }
    #pragma unroll
    for (int i = 0; i < 8; i++) {
        float* cp = C + (size_t)(m0 + ty * 8 + i) * ldc + n0 + tx * 8;
        float v[8];
        #pragma unroll
        for (int j = 0; j < 8; j++)
            v[j] = fmaxf(acc[i][j] + bias[n0 + tx * 8 + j], 0.f);
        *(float4*)(cp)     = make_float4(v[0], v[1], v[2], v[3]);
        *(float4*)(cp + 4) = make_float4(v[4], v[5], v[6], v[7]);
    }
}

// ---------------- gating: logits + softmax + top-8 + routing ----------------
__global__ void gate_route_kernel(const float* __restrict__ h,
                                  const float* __restrict__ w2,
                                  const float* __restrict__ b2)
{
    __shared__ float hs[H_GATE];
    __shared__ float red[E_EXP];
    __shared__ int   ridx[E_EXP];
    __shared__ float pv[E_EXP];
    __shared__ float selw[TOPK];
    __shared__ int   seli[TOPK];

    const int t = blockIdx.x;
    const int tid = threadIdx.x;

    for (int i = tid; i < H_GATE; i += E_EXP) hs[i] = h[(size_t)t * H_GATE + i];
    __syncthreads();

    float acc = b2[tid];
    #pragma unroll 8
    for (int kk = 0; kk < H_GATE; kk++)
        acc = fmaf(hs[kk], w2[kk * E_EXP + tid], acc);

    red[tid] = acc; __syncthreads();
    for (int s = 32; s > 0; s >>= 1) { if (tid < s) red[tid] = fmaxf(red[tid], red[tid + s]); __syncthreads(); }
    float m = red[0]; __syncthreads();
    float p = expf(acc - m);
    red[tid] = p; __syncthreads();
    for (int s = 32; s > 0; s >>= 1) { if (tid < s) red[tid] += red[tid + s]; __syncthreads(); }
    float sum = red[0]; __syncthreads();
    p /= sum;
    g_probs[t * E_EXP + tid] = p;

    pv[tid] = p; __syncthreads();
    for (int k = 0; k < TOPK; k++) {
        red[tid] = pv[tid]; ridx[tid] = tid; __syncthreads();
        for (int s = 32; s > 0; s >>= 1) {
            if (tid < s) {
                if (red[tid + s] > red[tid] ||
                    (red[tid + s] == red[tid] && ridx[tid + s] < ridx[tid])) {
                    red[tid] = red[tid + s]; ridx[tid] = ridx[tid + s];
                }
            }
            __syncthreads();
        }
        if (tid == 0) { seli[k] = ridx[0]; selw[k] = red[0]; pv[ridx[0]] = -1.f; }
        __syncthreads();
    }

    if (tid == 0) {
        float s8 = 0.f;
        #pragma unroll
        for (int k = 0; k < TOPK; k++) s8 += selw[k];
        float inv = 1.f / s8;
        for (int k = 0; k < TOPK; k++) {
            int ee = seli[k];
            g_topkw[t * TOPK + k] = selw[k] * inv;
            int pos = atomicAdd(&g_count[ee], 1);
            g_list_t[ee * T_TOK + pos] = t;
            g_list_p[ee * T_TOK + pos] = t * TOPK + k;
        }
    }
}

// ---------------- load-balance loss (coalesced two-phase) --------------------
__global__ void usage_part()
{
    __shared__ float red[4][E_EXP];
    const int b   = blockIdx.x;       // 0..31, 64 tokens each
    const int e   = threadIdx.x & 63;
    const int sub = threadIdx.x >> 6; // 0..3
    float s = 0.f;
    #pragma unroll
    for (int i = 0; i < 16; i++) {
        int t = b * 64 + i * 4 + sub;
        s += g_probs[t * E_EXP + e];
    }
    red[sub][e] = s; __syncthreads();
    if (sub == 0)
        g_part[b][e] = red[0][e] + red[1][e] + red[2][e] + red[3][e];
}
__global__ void lb_final(float* __restrict__ out, int out_size)
{
    __shared__ float red[E_EXP];
    const int e = threadIdx.x;
    float s = 0.f;
    #pragma unroll
    for (int b = 0; b < UPART; b++) s += g_part[b][e];
    float u = s / (float)T_TOK - 1.f / (float)E_EXP;
    red[e] = u * u; __syncthreads();
    for (int st = 32; st > 0; st >>= 1) { if (e < st) red[e] += red[e + st]; __syncthreads(); }
    if (e == 0 && out_size > T_TOK * DM)
        out[T_TOK * DM] = 0.01f * red[0] / (float)E_EXP;
}

// ---------------- weighted combine -------------------------------------------
__global__ void combine_kernel(float* __restrict__ out)
{
    const int t = blockIdx.x;
    for (int d = threadIdx.x; d < DM; d += 256) {
        float a = 0.f;
        #pragma unroll
        for (int k = 0; k < TOPK; k++)
            a = fmaf(g_topkw[t * TOPK + k],
                     g_ybuf[(size_t)(t * TOPK + k) * DM + d], a);
        out[(size_t)t * DM + d] = a;
    }
}

__global__ void zero_counts() { g_count[threadIdx.x] = 0; }

// ---------------- launch ------------------------------------------------------
extern "C" void kernel_launch(void* const* d_in, const int* in_sizes, int n_in,
                              void* d_out, int out_size)
{
    const float* x   = (const float*)d_in[0];
    const float* gw1 = (const float*)d_in[1];
    const float* gb1 = (const float*)d_in[2];
    const float* gw2 = (const float*)d_in[3];
    const float* gb2 = (const float*)d_in[4];
    const float* ew1 = (const float*)d_in[5];
    const float* eb1 = (const float*)d_in[6];
    const float* ew2 = (const float*)d_in[7];
    const float* eb2 = (const float*)d_in[8];
    float* out = (float*)d_out;

    float *ph, *pybuf;
    __half *phid, *px16, *pw1h, *pw2h;
    int *pcnt, *plt, *plp;
    cudaGetSymbolAddress((void**)&ph,    g_h);
    cudaGetSymbolAddress((void**)&phid,  g_hidden16);
    cudaGetSymbolAddress((void**)&px16,  g_x16);
    cudaGetSymbolAddress((void**)&pw1h,  g_w1h);
    cudaGetSymbolAddress((void**)&pw2h,  g_w2h);
    cudaGetSymbolAddress((void**)&pybuf, g_ybuf);
    cudaGetSymbolAddress((void**)&pcnt,  g_count);
    cudaGetSymbolAddress((void**)&plt,   g_list_t);
    cudaGetSymbolAddress((void**)&plp,   g_list_p);

    const int SMEM_DYN = 3 * 32768;   // 96 KB
    cudaFuncSetAttribute((const void*)mma_gemm16<__half, 2>,
                         cudaFuncAttributeMaxDynamicSharedMemorySize, SMEM_DYN);
    cudaFuncSetAttribute((const void*)mma_gemm16<float, 0>,
                         cudaFuncAttributeMaxDynamicSharedMemorySize, SMEM_DYN);

    zero_counts<<<1, E_EXP>>>();

    // fp16 conversions (grid-stride, DRAM-saturating)
    {
        int n8w = (E_EXP * DM * H_EXP) / 8;
        cvt16<<<4096, 256>>>((const float4*)ew1, (uint4*)pw1h, n8w);
        cvt16<<<4096, 256>>>((const float4*)ew2, (uint4*)pw2h, n8w);
        int n8x = (T_TOK * DM) / 8;
        cvt16<<<512, 256>>>((const float4*)x, (uint4*)px16, n8x);
    }

    // gate layer 1 (exact fp32 — routing depends on it; PINNED)
    sgemm_relu<<<dim3(T_TOK/128, H_GATE/128), 256>>>(x, DM, DM, gw1, H_GATE, gb1, ph, H_GATE);

    gate_route_kernel<<<T_TOK, E_EXP>>>(ph, gw2, gb2);

    usage_part<<<UPART, 256>>>();
    lb_final<<<1, E_EXP>>>(out, out_size);

    // expert GEMM 1: hidden16 = gelu(x16[list] @ w1h[e] + eb1[e])
    mma_gemm16<__half, 2><<<dim3(T_TOK/128, H_EXP/128, E_EXP), 256, SMEM_DYN>>>(
        px16, DM, DM, pw1h, (size_t)DM * H_EXP, H_EXP, eb1, H_EXP,
        phid, H_EXP, plt, plp, pcnt, 0);

    // expert GEMM 2: ybuf = hidden16[list] @ w2h[e] + eb2[e]
    mma_gemm16<float, 0><<<dim3(T_TOK/128, DM/128, E_EXP), 256, SMEM_DYN>>>(
        phid, H_EXP, H_EXP, pw2h, (size_t)H_EXP * DM, DM, eb2, DM,
        pybuf, DM, plp, plp, pcnt, 0);

    combine_kernel<<<T_TOK, 256>>>(out);
}

// round 9
// speedup vs baseline: 1.4583x; 1.0326x over previous
#include <cuda_runtime.h>
#include <cuda_fp16.h>
#include <math.h>
#include <stdint.h>

#define T_TOK   2048
#define DM      512
#define E_EXP   64
#define TOPK    8
#define H_GATE  1024
#define H_EXP   2048
#define NPAIR   (T_TOK*TOPK)
#define UPART   32

// ---------------- scratch (device globals) ----------------------------------
static __device__ float  g_h[(size_t)T_TOK * H_GATE];        // gate hidden fp32
static __device__ float  g_probs[T_TOK * E_EXP];
static __device__ float  g_topkw[T_TOK * TOPK];
static __device__ float  g_part[UPART][E_EXP];
static __device__ int    g_count[E_EXP];
static __device__ int    g_list_t[E_EXP * T_TOK];
static __device__ int    g_list_p[E_EXP * T_TOK];
static __device__ __half g_x16[(size_t)T_TOK * DM];          // x_hi (2 MiB)
static __device__ __half g_xlo[(size_t)T_TOK * DM];          // x_lo (2 MiB)
static __device__ __half g_gw1hi[(size_t)DM * H_GATE];       // 1 MiB
static __device__ __half g_gw1lo[(size_t)DM * H_GATE];       // 1 MiB
static __device__ __half g_w1h[(size_t)E_EXP * DM * H_EXP];  // 128 MiB
static __device__ __half g_w2h[(size_t)E_EXP * H_EXP * DM];  // 128 MiB
static __device__ __half g_hidden16[(size_t)NPAIR * H_EXP];  // 64 MiB
static __device__ float  g_ybuf[(size_t)NPAIR * DM];         // 32 MiB

// ---------------- helpers ----------------------------------------------------
__device__ __forceinline__ uint32_t smem_u32(const void* p) {
    uint32_t a;
    asm("{ .reg .u64 t; cvta.to.shared.u64 t, %1; cvt.u32.u64 %0, t; }" : "=r"(a) : "l"(p));
    return a;
}
__device__ __forceinline__ uint32_t packh(float lo, float hi) {
    uint32_t r;
    asm("cvt.rn.f16x2.f32 %0, %1, %2;" : "=r"(r) : "f"(hi), "f"(lo));
    return r;
}
__device__ __forceinline__ void cp16(uint32_t dst, const void* src, int srcsize) {
    asm volatile("cp.async.cg.shared.global [%0], [%1], 16, %2;"
                 :: "r"(dst), "l"(src), "r"(srcsize) : "memory");
}
__device__ __forceinline__ void cp_commit() {
    asm volatile("cp.async.commit_group;" ::: "memory");
}
__device__ __forceinline__ void ldsm4(uint32_t* r, uint32_t addr) {
    asm volatile("ldmatrix.sync.aligned.m8n8.x4.shared.b16 {%0,%1,%2,%3}, [%4];"
                 : "=r"(r[0]), "=r"(r[1]), "=r"(r[2]), "=r"(r[3]) : "r"(addr));
}
__device__ __forceinline__ void ldsm4t(uint32_t* r, uint32_t addr) {
    asm volatile("ldmatrix.sync.aligned.m8n8.x4.trans.shared.b16 {%0,%1,%2,%3}, [%4];"
                 : "=r"(r[0]), "=r"(r[1]), "=r"(r[2]), "=r"(r[3]) : "r"(addr));
}
__device__ __forceinline__ void mma_f16(float* c, const uint32_t* a, uint32_t b0, uint32_t b1) {
    asm volatile(
        "mma.sync.aligned.m16n8k16.row.col.f32.f16.f16.f32 "
        "{%0,%1,%2,%3}, {%4,%5,%6,%7}, {%8,%9}, {%0,%1,%2,%3};"
        : "+f"(c[0]), "+f"(c[1]), "+f"(c[2]), "+f"(c[3])
        : "r"(a[0]), "r"(a[1]), "r"(a[2]), "r"(a[3]), "r"(b0), "r"(b1));
}

// ---------------- fp32 -> fp16 bulk convert (grid-stride) --------------------
__global__ void cvt16(const float4* __restrict__ in, uint4* __restrict__ out, int n8)
{
    int stride = gridDim.x * blockDim.x;
    for (int i = blockIdx.x * blockDim.x + threadIdx.x; i < n8; i += stride) {
        float4 v0 = __ldg(&in[2 * i]);
        float4 v1 = __ldg(&in[2 * i + 1]);
        uint4 o;
        o.x = packh(v0.x, v0.y); o.y = packh(v0.z, v0.w);
        o.z = packh(v1.x, v1.y); o.w = packh(v1.z, v1.w);
        out[i] = o;
    }
}

// ---------------- fp32 -> (hi, lo) fp16 split --------------------------------
__global__ void cvt_split(const float4* __restrict__ in,
                          uint2* __restrict__ hi, uint2* __restrict__ lo, int n4)
{
    int stride = gridDim.x * blockDim.x;
    for (int i = blockIdx.x * blockDim.x + threadIdx.x; i < n4; i += stride) {
        float4 v = __ldg(&in[i]);
        __half hx = __float2half_rn(v.x), hy = __float2half_rn(v.y);
        __half hz = __float2half_rn(v.z), hw = __float2half_rn(v.w);
        uint2 h, l;
        h.x = packh(__half2float(hx), __half2float(hy));
        h.y = packh(__half2float(hz), __half2float(hw));
        // pack exact hi bits (round-trip through float is exact for fp16)
        l.x = packh(v.x - __half2float(hx), v.y - __half2float(hy));
        l.y = packh(v.z - __half2float(hz), v.w - __half2float(hw));
        hi[i] = h; lo[i] = l;
    }
}

// ---------------- all-fp16 grouped GEMM: cp.async + ldmatrix + HMMA ----------
// C[out(r), n] = act( [C_old +] sum_k A[in(r), k] * B[e][k, n] + bias[e][n] )
// Tile 128x128, BK=64, 8 warps (32x64). ACT: 0 none, 1 relu, 2 gelu. ACC: +=C.
template<typename OT, int ACT, int ACC>
__global__ __launch_bounds__(256, 2)
void mma_gemm16(const __half* __restrict__ A, int lda, int K,
                const __half* __restrict__ Bbase, size_t strideB, int N,
                const float* __restrict__ biasBase, int strideBias,
                OT* __restrict__ C, int ldc,
                const int* __restrict__ rowlist, const int* __restrict__ outlist,
                const int* __restrict__ cnts, int Mfixed)
{
    const int e  = blockIdx.z;
    const int M  = cnts ? cnts[e] : Mfixed;
    const int m0 = blockIdx.x * 128;
    if (m0 >= M) return;
    const int n0 = blockIdx.y * 128;

    extern __shared__ char sm[];
    const uint32_t smBytes = smem_u32(sm);

    const int tid  = threadIdx.x;
    const int wid  = tid >> 5;
    const int lane = tid & 31;
    const int wy   = wid & 3;
    const int wx   = wid >> 2;
    const int g    = lane >> 2;
    const int tig  = lane & 3;

    const int* rl = rowlist ? rowlist + e * T_TOK : nullptr;
    const int* ol = outlist ? outlist + e * T_TOK : nullptr;

    const __half* aSrc[4]; int aSz[4];
    uint32_t aOff0, bOff0;
    const __half* bSrc0;
    {
        int ar = tid >> 3, s = tid & 7;
        aOff0 = (uint32_t)(ar * 128 + 16 * (s ^ (ar & 7)));
        #pragma unroll
        for (int j = 0; j < 4; j++) {
            int gm = m0 + ar + j * 32;
            if (gm < M) { aSrc[j] = A + (size_t)(rl ? rl[gm] : gm) * lda + s * 8; aSz[j] = 16; }
            else        { aSrc[j] = A;                                            aSz[j] = 0;  }
        }
        int bk = tid >> 4, s2 = tid & 15;
        bOff0 = 16384u + (uint32_t)(bk * 256 + 16 * (s2 ^ (bk & 7)));
        bSrc0 = Bbase + (size_t)e * strideB + (size_t)bk * N + n0 + s2 * 8;
    }

    const int NC = K / 64;
    const size_t bStep = (size_t)64 * N;

    #define ISSUE(cc) do { \
        uint32_t st = smBytes + (uint32_t)((cc) % 3) * 32768u; \
        _Pragma("unroll") \
        for (int j = 0; j < 4; j++) \
            cp16(st + aOff0 + (uint32_t)j * 4096u, aSrc[j] + (size_t)(cc) * 64, aSz[j]); \
        _Pragma("unroll") \
        for (int j = 0; j < 4; j++) \
            cp16(st + bOff0 + (uint32_t)j * 4096u, bSrc0 + (size_t)j * 16 * N + (size_t)(cc) * bStep, 16); \
        cp_commit(); \
    } while (0)

    ISSUE(0);
    if (NC > 1) ISSUE(1);

    float acc[2][8][4];
    #pragma unroll
    for (int fm = 0; fm < 2; fm++)
        #pragma unroll
        for (int fn = 0; fn < 8; fn++)
            #pragma unroll
            for (int q = 0; q < 4; q++) acc[fm][fn][q] = 0.f;

    const int mlane = wy * 32 + (lane & 15);
    const int aksel = (lane >> 4) & 1;
    const int bklan = lane & 15;
    const int bnsel = ((lane >> 4) & 1) * 8;

    for (int c = 0; c < NC; c++) {
        if (c + 1 < NC) asm volatile("cp.async.wait_group 1;" ::: "memory");
        else            asm volatile("cp.async.wait_group 0;" ::: "memory");
        __syncthreads();

        if (c + 2 < NC) ISSUE(c + 2);

        const uint32_t stA = smBytes + (uint32_t)(c % 3) * 32768u;
        const uint32_t stB = stA + 16384u;

        #pragma unroll
        for (int ks = 0; ks < 4; ks++) {
            const int aseg = ks * 2 + aksel;
            uint32_t a0[4], a1[4];
            {
                int m = mlane;
                ldsm4(a0, stA + m * 128 + 16 * (aseg ^ (m & 7)));
                m = mlane + 16;
                ldsm4(a1, stA + m * 128 + 16 * (aseg ^ (m & 7)));
            }
            const int kk = ks * 16 + bklan;
            const uint32_t brow = stB + kk * 256;
            const int ksw = kk & 7;
            #pragma unroll
            for (int nb = 0; nb < 4; nb++) {
                int nseg = (wx * 64 + nb * 16 + bnsel) >> 3;
                uint32_t bb[4];
                ldsm4t(bb, brow + 16 * (nseg ^ ksw));
                mma_f16(acc[0][2 * nb],     a0, bb[0], bb[1]);
                mma_f16(acc[1][2 * nb],     a1, bb[0], bb[1]);
                mma_f16(acc[0][2 * nb + 1], a0, bb[2], bb[3]);
                mma_f16(acc[1][2 * nb + 1], a1, bb[2], bb[3]);
            }
        }
        __syncthreads();
    }
    #undef ISSUE

    // ---- epilogue -----------------------------------------------------------
    const float* bias = biasBase ? biasBase + (size_t)e * strideBias + n0 : nullptr;
    #pragma unroll
    for (int fm = 0; fm < 2; fm++) {
        int r0 = m0 + wy * 32 + fm * 16 + g;
        #pragma unroll
        for (int half = 0; half < 2; half++) {
            int row = r0 + half * 8;
            if (row >= M) continue;
            int orow = ol ? ol[row] : row;
            OT* cp = C + (size_t)orow * ldc + n0;
            #pragma unroll
            for (int fn = 0; fn < 8; fn++) {
                int col = wx * 64 + fn * 8 + 2 * tig;
                float v0 = acc[fm][fn][half * 2 + 0] + (bias ? bias[col]     : 0.f);
                float v1 = acc[fm][fn][half * 2 + 1] + (bias ? bias[col + 1] : 0.f);
                if (ACC && sizeof(OT) == 4) {
                    float2 old = *(float2*)((float*)cp + col);
                    v0 += old.x; v1 += old.y;
                }
                if (ACT == 1) { v0 = fmaxf(v0, 0.f); v1 = fmaxf(v1, 0.f); }
                if (ACT == 2) {
                    v0 = 0.5f * v0 * (1.f + erff(v0 * 0.70710678118654752f));
                    v1 = 0.5f * v1 * (1.f + erff(v1 * 0.70710678118654752f));
                }
                if (sizeof(OT) == 4) {
                    *(float2*)((float*)cp + col) = make_float2(v0, v1);
                } else {
                    *(uint32_t*)((__half*)cp + col) = packh(v0, v1);
                }
            }
        }
    }
}

// ---------------- gating: warp-per-token logits + softmax + top-8 ------------
__global__ __launch_bounds__(256)
void gate_route_kernel(const float* __restrict__ h,
                       const float* __restrict__ w2,
                       const float* __restrict__ b2)
{
    __shared__ float hs[8][H_GATE];
    const int warp = threadIdx.x >> 5;
    const int lane = threadIdx.x & 31;
    const int t0 = blockIdx.x * 8;

    for (int i = threadIdx.x; i < 8 * H_GATE; i += 256)
        hs[i >> 10][i & (H_GATE - 1)] = h[(size_t)(t0 + (i >> 10)) * H_GATE + (i & (H_GATE - 1))];
    __syncthreads();

    const int t = t0 + warp;
    float a0 = b2[lane], a1 = b2[lane + 32];
    const float* hrow = hs[warp];
    #pragma unroll 4
    for (int kk = 0; kk < H_GATE; kk++) {
        float hv = hrow[kk];
        a0 = fmaf(hv, __ldg(&w2[kk * E_EXP + lane]),      a0);
        a1 = fmaf(hv, __ldg(&w2[kk * E_EXP + lane + 32]), a1);
    }

    // softmax over 64 values (2 per lane)
    float mx = fmaxf(a0, a1);
    #pragma unroll
    for (int s = 16; s; s >>= 1) mx = fmaxf(mx, __shfl_xor_sync(~0u, mx, s));
    float p0 = expf(a0 - mx), p1 = expf(a1 - mx);
    float sum = p0 + p1;
    #pragma unroll
    for (int s = 16; s; s >>= 1) sum += __shfl_xor_sync(~0u, sum, s);
    p0 /= sum; p1 /= sum;
    g_probs[t * E_EXP + lane]      = p0;
    g_probs[t * E_EXP + lane + 32] = p1;

    // top-8 via warp argmax (ties -> lower index)
    float v0 = p0, v1 = p1;
    float selw[TOPK]; int seli[TOPK];
    #pragma unroll
    for (int k = 0; k < TOPK; k++) {
        float v; int idx;
        if (v0 >= v1) { v = v0; idx = lane; } else { v = v1; idx = lane + 32; }
        #pragma unroll
        for (int s = 16; s; s >>= 1) {
            float ov = __shfl_xor_sync(~0u, v, s);
            int   oi = __shfl_xor_sync(~0u, idx, s);
            if (ov > v || (ov == v && oi < idx)) { v = ov; idx = oi; }
        }
        selw[k] = v; seli[k] = idx;
        if (idx == lane) v0 = -1.f;
        else if (idx == lane + 32) v1 = -1.f;
    }

    if (lane == 0) {
        float s8 = 0.f;
        #pragma unroll
        for (int k = 0; k < TOPK; k++) s8 += selw[k];
        float inv = 1.f / s8;
        #pragma unroll
        for (int k = 0; k < TOPK; k++) {
            int ee = seli[k];
            g_topkw[t * TOPK + k] = selw[k] * inv;
            int pos = atomicAdd(&g_count[ee], 1);
            g_list_t[ee * T_TOK + pos] = t;
            g_list_p[ee * T_TOK + pos] = t * TOPK + k;
        }
    }
}

// ---------------- load-balance loss (coalesced two-phase) --------------------
__global__ void usage_part()
{
    __shared__ float red[4][E_EXP];
    const int b   = blockIdx.x;
    const int e   = threadIdx.x & 63;
    const int sub = threadIdx.x >> 6;
    float s = 0.f;
    #pragma unroll
    for (int i = 0; i < 16; i++) {
        int t = b * 64 + i * 4 + sub;
        s += g_probs[t * E_EXP + e];
    }
    red[sub][e] = s; __syncthreads();
    if (sub == 0)
        g_part[b][e] = red[0][e] + red[1][e] + red[2][e] + red[3][e];
}
__global__ void lb_final(float* __restrict__ out, int out_size)
{
    __shared__ float red[E_EXP];
    const int e = threadIdx.x;
    float s = 0.f;
    #pragma unroll
    for (int b = 0; b < UPART; b++) s += g_part[b][e];
    float u = s / (float)T_TOK - 1.f / (float)E_EXP;
    red[e] = u * u; __syncthreads();
    for (int st = 32; st > 0; st >>= 1) { if (e < st) red[e] += red[e + st]; __syncthreads(); }
    if (e == 0 && out_size > T_TOK * DM)
        out[T_TOK * DM] = 0.01f * red[0] / (float)E_EXP;
}

// ---------------- weighted combine (float4, one token per block) -------------
__global__ __launch_bounds__(128)
void combine_kernel(float* __restrict__ out)
{
    const int t = blockIdx.x;
    const int d4 = threadIdx.x;                 // 0..127 -> float4 lane
    const float4* yb = (const float4*)g_ybuf;
    float4 a = make_float4(0.f, 0.f, 0.f, 0.f);
    #pragma unroll
    for (int k = 0; k < TOPK; k++) {
        float w = g_topkw[t * TOPK + k];
        float4 y = yb[(size_t)(t * TOPK + k) * (DM / 4) + d4];
        a.x = fmaf(w, y.x, a.x); a.y = fmaf(w, y.y, a.y);
        a.z = fmaf(w, y.z, a.z); a.w = fmaf(w, y.w, a.w);
    }
    ((float4*)out)[(size_t)t * (DM / 4) + d4] = a;
}

__global__ void zero_counts() { g_count[threadIdx.x] = 0; }

// ---------------- launch ------------------------------------------------------
extern "C" void kernel_launch(void* const* d_in, const int* in_sizes, int n_in,
                              void* d_out, int out_size)
{
    const float* x   = (const float*)d_in[0];
    const float* gw1 = (const float*)d_in[1];
    const float* gb1 = (const float*)d_in[2];
    const float* gw2 = (const float*)d_in[3];
    const float* gb2 = (const float*)d_in[4];
    const float* ew1 = (const float*)d_in[5];
    const float* eb1 = (const float*)d_in[6];
    const float* ew2 = (const float*)d_in[7];
    const float* eb2 = (const float*)d_in[8];
    float* out = (float*)d_out;

    float *ph, *pybuf;
    __half *phid, *px16, *pxlo, *pg1hi, *pg1lo, *pw1h, *pw2h;
    int *pcnt, *plt, *plp;
    cudaGetSymbolAddress((void**)&ph,    g_h);
    cudaGetSymbolAddress((void**)&phid,  g_hidden16);
    cudaGetSymbolAddress((void**)&px16,  g_x16);
    cudaGetSymbolAddress((void**)&pxlo,  g_xlo);
    cudaGetSymbolAddress((void**)&pg1hi, g_gw1hi);
    cudaGetSymbolAddress((void**)&pg1lo, g_gw1lo);
    cudaGetSymbolAddress((void**)&pw1h,  g_w1h);
    cudaGetSymbolAddress((void**)&pw2h,  g_w2h);
    cudaGetSymbolAddress((void**)&pybuf, g_ybuf);
    cudaGetSymbolAddress((void**)&pcnt,  g_count);
    cudaGetSymbolAddress((void**)&plt,   g_list_t);
    cudaGetSymbolAddress((void**)&plp,   g_list_p);

    const int SMEM_DYN = 3 * 32768;   // 96 KB
    cudaFuncSetAttribute((const void*)mma_gemm16<__half, 2, 0>,
                         cudaFuncAttributeMaxDynamicSharedMemorySize, SMEM_DYN);
    cudaFuncSetAttribute((const void*)mma_gemm16<float, 0, 0>,
                         cudaFuncAttributeMaxDynamicSharedMemorySize, SMEM_DYN);
    cudaFuncSetAttribute((const void*)mma_gemm16<float, 0, 1>,
                         cudaFuncAttributeMaxDynamicSharedMemorySize, SMEM_DYN);
    cudaFuncSetAttribute((const void*)mma_gemm16<float, 1, 1>,
                         cudaFuncAttributeMaxDynamicSharedMemorySize, SMEM_DYN);

    zero_counts<<<1, E_EXP>>>();

    // conversions
    {
        int n8w = (E_EXP * DM * H_EXP) / 8;
        cvt16<<<4096, 256>>>((const float4*)ew1, (uint4*)pw1h, n8w);
        cvt16<<<4096, 256>>>((const float4*)ew2, (uint4*)pw2h, n8w);
        int n4x = (T_TOK * DM) / 4;
        cvt_split<<<512, 256>>>((const float4*)x, (uint2*)px16, (uint2*)pxlo, n4x);
        int n4g = (DM * H_GATE) / 4;
        cvt_split<<<512, 256>>>((const float4*)gw1, (uint2*)pg1hi, (uint2*)pg1lo, n4g);
    }

    // gate layer 1, error-compensated fp16 split (fp32-class precision):
    // h = relu( x_hi*w_hi + x_hi*w_lo + x_lo*w_hi + b1 )
    dim3 ggrid(T_TOK / 128, H_GATE / 128, 1);
    mma_gemm16<float, 0, 0><<<ggrid, 256, SMEM_DYN>>>(
        px16, DM, DM, pg1hi, 0, H_GATE, nullptr, 0,
        ph, H_GATE, nullptr, nullptr, nullptr, T_TOK);
    mma_gemm16<float, 0, 1><<<ggrid, 256, SMEM_DYN>>>(
        px16, DM, DM, pg1lo, 0, H_GATE, nullptr, 0,
        ph, H_GATE, nullptr, nullptr, nullptr, T_TOK);
    mma_gemm16<float, 1, 1><<<ggrid, 256, SMEM_DYN>>>(
        pxlo, DM, DM, pg1hi, 0, H_GATE, gb1, 0,
        ph, H_GATE, nullptr, nullptr, nullptr, T_TOK);

    gate_route_kernel<<<T_TOK / 8, 256>>>(ph, gw2, gb2);

    usage_part<<<UPART, 256>>>();
    lb_final<<<1, E_EXP>>>(out, out_size);

    // expert GEMM 1: hidden16 = gelu(x16[list] @ w1h[e] + eb1[e])
    mma_gemm16<__half, 2, 0><<<dim3(T_TOK/128, H_EXP/128, E_EXP), 256, SMEM_DYN>>>(
        px16, DM, DM, pw1h, (size_t)DM * H_EXP, H_EXP, eb1, H_EXP,
        phid, H_EXP, plt, plp, pcnt, 0);

    // expert GEMM 2: ybuf = hidden16[list] @ w2h[e] + eb2[e]
    mma_gemm16<float, 0, 0><<<dim3(T_TOK/128, DM/128, E_EXP), 256, SMEM_DYN>>>(
        phid, H_EXP, H_EXP, pw2h, (size_t)H_EXP * DM, DM, eb2, DM,
        pybuf, DM, plp, plp, pcnt, 0);

    combine_kernel<<<T_TOK, 128>>>(out);
}